// round 14
// baseline (speedup 1.0000x reference)
#include <cuda_runtime.h>
#include <cuda_fp16.h>

#define N_NODES 50000
#define HF 128          // H*F
#define H_HEADS 4
#define DEG_CAP 128     // bucket capacity; deg ~ Poisson(16), P(>128) < 1e-60
#define GBLK 128        // nodes per GEMM block
#define KCH 32          // K chunk
#define WROW 130        // ws2 row stride in float2 (pad keeps 16B alignment, spreads banks)

// ---------------- packed f32x2 helpers (sm_103a) ----------------
#define UNPACK_F32X2(lo, hi, in) \
    asm("mov.b64 {%0, %1}, %2;" : "=f"(lo), "=f"(hi) : "l"(in))
#define FMA_F32X2(d, a, b, c) \
    asm("fma.rn.f32x2 %0, %1, %2, %3;" : "=l"(d) : "l"(a), "l"(b), "l"(c))

// ---------------- scratch (static device globals; no allocation) ----------------
__device__ float g_z[N_NODES * HF];
__device__ float g_acc1[N_NODES * HF];   // layer-1 base -> elu(h1)
__device__ float g_acc2[N_NODES * HF];   // layer-2 base (residual + bias)
__device__ float g_el[N_NODES * H_HEADS];
__device__ float g_er[N_NODES * H_HEADS];
__device__ int   g_cnt[N_NODES];
__device__ int   g_bucket[N_NODES * DEG_CAP];   // 25.6 MB

__device__ __forceinline__ float leaky(float v) { return v > 0.f ? v : 0.2f * v; }
__device__ __forceinline__ float elu(float v)   { return v > 0.f ? v : (__expf(v) - 1.f); }

// ---------------- bucket fill: the entire adjacency build in one kernel ----------------
__global__ void fill_bucket_kernel(const int* __restrict__ src, const int* __restrict__ dst,
                                   int E, int* __restrict__ cnt, int* __restrict__ bucket) {
    int i = blockIdx.x * blockDim.x + threadIdx.x;
    int e0 = i * 4;
    if (e0 + 4 <= E) {
        int4 d4 = *reinterpret_cast<const int4*>(dst + e0);
        int4 s4 = *reinterpret_cast<const int4*>(src + e0);
        int p0 = atomicAdd(&cnt[d4.x], 1);
        int p1 = atomicAdd(&cnt[d4.y], 1);
        int p2 = atomicAdd(&cnt[d4.z], 1);
        int p3 = atomicAdd(&cnt[d4.w], 1);
        bucket[d4.x * DEG_CAP + p0] = s4.x;
        bucket[d4.y * DEG_CAP + p1] = s4.y;
        bucket[d4.z * DEG_CAP + p2] = s4.z;
        bucket[d4.w * DEG_CAP + p3] = s4.w;
    } else {
        for (int e = e0; e < E; e++) {
            int dn = dst[e];
            int pos = atomicAdd(&cnt[dn], 1);
            bucket[dn * DEG_CAP + pos] = src[e];
        }
    }
}

// ---------------- K1: register-tiled SGEMM with packed f32x2 (node pairs) ---------------
// 256 threads, 128x128 tile, 8 nodes x 8 cols per thread as 4 node-pair x 8 col FFMA2.
// xs[k][node] gives node-pairs natively; W pre-splatted {w,w} in smem -> no packing MOVs.
__global__ __launch_bounds__(256)
void gemm_attn_kernel(const float* __restrict__ x,
                      const float* __restrict__ W,
                      const float* __restrict__ al,
                      const float* __restrict__ ar,
                      const float* __restrict__ bias,
                      float* __restrict__ z,
                      float* __restrict__ base,
                      float* __restrict__ el,
                      float* __restrict__ er)
{
    __shared__ float  xs[KCH][GBLK];      // x chunk, transposed: xs[k][node]  (16 KB)
    __shared__ float2 ws2[KCH][WROW];     // W chunk splatted: ws2[k][col]={w,w} (32.5 KB)

    const int tid = threadIdx.x;
    const int n0  = blockIdx.x * GBLK;
    const int cg  = tid & 15;             // col octet: cols cg*8..cg*8+7
    const int ng  = tid >> 4;             // node octet: nodes n0+ng*8..+7

    unsigned long long acc[4][8];         // [node-pair][col], f32x2 packed
    #pragma unroll
    for (int rp = 0; rp < 4; rp++)
        #pragma unroll
        for (int c = 0; c < 8; c++) acc[rp][c] = 0ull;

    const int lrow = tid & 127;           // node row for x loads
    const int c4b  = tid >> 7;            // 0..1

    for (int kc = 0; kc < HF; kc += KCH) {
        // ---- load x chunk (transposed) + write base = x + bias ----
        {
            const int n = n0 + lrow;
            const bool valid = (n < N_NODES);
            #pragma unroll
            for (int it = 0; it < 4; it++) {
                int c4 = c4b + it * 2;            // 0..7 (float4 within chunk)
                int k  = kc + c4 * 4;
                float4 v = make_float4(0.f, 0.f, 0.f, 0.f);
                if (valid) v = *reinterpret_cast<const float4*>(&x[n * HF + k]);
                xs[c4 * 4 + 0][lrow] = v.x;
                xs[c4 * 4 + 1][lrow] = v.y;
                xs[c4 * 4 + 2][lrow] = v.z;
                xs[c4 * 4 + 3][lrow] = v.w;
                if (valid) {
                    float4 b4 = *reinterpret_cast<const float4*>(&bias[k]);
                    float4 o = make_float4(v.x + b4.x, v.y + b4.y, v.z + b4.z, v.w + b4.w);
                    *reinterpret_cast<float4*>(&base[n * HF + k]) = o;
                }
            }
        }
        // ---- load W chunk, splatted {w,w} ----
        {
            #pragma unroll
            for (int it = 0; it < 4; it++) {
                int idx = tid + it * 256;          // float4 index, 0..1023
                int kl  = idx >> 5;                // 32 float4 per k-row
                int c4  = idx & 31;
                float4 v = *reinterpret_cast<const float4*>(&W[(kc + kl) * HF + c4 * 4]);
                ws2[kl][c4 * 4 + 0] = make_float2(v.x, v.x);
                ws2[kl][c4 * 4 + 1] = make_float2(v.y, v.y);
                ws2[kl][c4 * 4 + 2] = make_float2(v.z, v.z);
                ws2[kl][c4 * 4 + 3] = make_float2(v.w, v.w);
            }
        }
        __syncthreads();

        // ---- packed outer-product over the chunk: 6 LDS.128 + 32 FFMA2 per k ----
        #pragma unroll
        for (int k = 0; k < KCH; k++) {
            ulonglong2 x01 = *reinterpret_cast<const ulonglong2*>(&xs[k][ng * 8]);
            ulonglong2 x23 = *reinterpret_cast<const ulonglong2*>(&xs[k][ng * 8 + 4]);
            ulonglong2 w01 = *reinterpret_cast<const ulonglong2*>(&ws2[k][cg * 8]);
            ulonglong2 w23 = *reinterpret_cast<const ulonglong2*>(&ws2[k][cg * 8 + 2]);
            ulonglong2 w45 = *reinterpret_cast<const ulonglong2*>(&ws2[k][cg * 8 + 4]);
            ulonglong2 w67 = *reinterpret_cast<const ulonglong2*>(&ws2[k][cg * 8 + 6]);
            unsigned long long xp[4] = { x01.x, x01.y, x23.x, x23.y };
            unsigned long long wp[8] = { w01.x, w01.y, w23.x, w23.y,
                                         w45.x, w45.y, w67.x, w67.y };
            #pragma unroll
            for (int rp = 0; rp < 4; rp++)
                #pragma unroll
                for (int c = 0; c < 8; c++)
                    FMA_F32X2(acc[rp][c], xp[rp], wp[c], acc[rp][c]);
        }
        __syncthreads();
    }

    // ---- epilogue: z store, el/er reductions (4-lane groups share a head) ----
    const int h  = cg >> 2;
    const int c0 = cg * 8;
    float alv[8], arv[8];
    #pragma unroll
    for (int c = 0; c < 8; c++) { alv[c] = al[c0 + c]; arv[c] = ar[c0 + c]; }

    #pragma unroll
    for (int rp = 0; rp < 4; rp++) {
        float lo[8], hi[8];
        #pragma unroll
        for (int c = 0; c < 8; c++) UNPACK_F32X2(lo[c], hi[c], acc[rp][c]);

        #pragma unroll
        for (int q = 0; q < 2; q++) {
            const float* rv = q ? hi : lo;
            int n = n0 + ng * 8 + rp * 2 + q;
            bool valid = (n < N_NODES);
            if (valid) {
                *reinterpret_cast<float4*>(&z[n * HF + c0]) =
                    make_float4(rv[0], rv[1], rv[2], rv[3]);
                *reinterpret_cast<float4*>(&z[n * HF + c0 + 4]) =
                    make_float4(rv[4], rv[5], rv[6], rv[7]);
            }
            float pl = 0.f, pr = 0.f;
            #pragma unroll
            for (int c = 0; c < 8; c++) { pl += rv[c] * alv[c]; pr += rv[c] * arv[c]; }
            pl += __shfl_down_sync(0xffffffffu, pl, 2);
            pl += __shfl_down_sync(0xffffffffu, pl, 1);
            pr += __shfl_down_sync(0xffffffffu, pr, 2);
            pr += __shfl_down_sync(0xffffffffu, pr, 1);
            if (valid && (cg & 3) == 0) {
                el[n * H_HEADS + h] = pl;
                er[n * H_HEADS + h] = pr;
            }
        }
    }
}

// ---------------- single-pass softmax-free aggregate, one warp per node -----------------
// h_n = base_n + (sum_i e_i * z_{src_i}) / (sum_i e_i).  R6-proven loop shape, fp32 z.
// MODE 0: layer-1 epilogue -> elu(acc) stored to hio (becomes layer-2 input)
// MODE 1: layer-2 epilogue -> head-mean + projection, writes out[n] only
template <int MODE>
__global__ __launch_bounds__(256)
void gat_aggregate_kernel(const int* __restrict__ cnt,
                          const int* __restrict__ bucket,
                          const float* __restrict__ el, const float* __restrict__ er,
                          const float* __restrict__ z,
                          float* __restrict__ hio,          // base in, result out (MODE 0)
                          const float* __restrict__ Wp, const float* __restrict__ bp,
                          float* __restrict__ out)
{
    const int wid  = threadIdx.x >> 5;
    const int lane = threadIdx.x & 31;
    const int n    = blockIdx.x * 8 + wid;
    if (n >= N_NODES) return;

    const int beg = n * DEG_CAP;
    const int d   = cnt[n];
    const int h   = lane >> 3;

    const float erh = __ldg(&er[n * H_HEADS + h]);

    float  s   = 0.f;
    float4 acc = make_float4(0.f, 0.f, 0.f, 0.f);

    for (int i = 0; i < d; ++i) {
        int   sn = __ldg(&bucket[beg + i]);                        // warp-uniform
        float ev = __expf(leaky(__ldg(&el[sn * H_HEADS + h]) + erh));
        float4 zv = *reinterpret_cast<const float4*>(z + sn * HF + lane * 4);
        s     += ev;
        acc.x += ev * zv.x;
        acc.y += ev * zv.y;
        acc.z += ev * zv.z;
        acc.w += ev * zv.w;
    }

    const float sinv = 1.f / fmaxf(s, 1e-9f);
    float4 base = *reinterpret_cast<const float4*>(hio + n * HF + lane * 4);
    acc.x = base.x + acc.x * sinv;
    acc.y = base.y + acc.y * sinv;
    acc.z = base.z + acc.z * sinv;
    acc.w = base.w + acc.w * sinv;

    if (MODE == 0) {
        // ELU here so layer-2 GEMM (and its residual) read the activated value directly
        acc.x = elu(acc.x); acc.y = elu(acc.y); acc.z = elu(acc.z); acc.w = elu(acc.w);
        *reinterpret_cast<float4*>(hio + n * HF + lane * 4) = acc;
    } else {
        // head-mean + projection: out[n] = 0.25 * sum_{h,f} acc[h][f] * Wp[f] + bp
        const int f0 = (lane & 7) * 4;
        float v = acc.x * Wp[f0] + acc.y * Wp[f0 + 1] + acc.z * Wp[f0 + 2] + acc.w * Wp[f0 + 3];
        #pragma unroll
        for (int off = 16; off; off >>= 1) v += __shfl_down_sync(0xffffffffu, v, off);
        if (lane == 0) out[n] = 0.25f * v + bp[0];
    }
}

// ---------------- launch ----------------
extern "C" void kernel_launch(void* const* d_in, const int* in_sizes, int n_in,
                              void* d_out, int out_size)
{
    const float* feats = (const float*)d_in[0];
    const int*   src   = (const int*)  d_in[1];
    const int*   dst   = (const int*)  d_in[2];
    const float* W1    = (const float*)d_in[3];
    const float* al1   = (const float*)d_in[4];
    const float* ar1   = (const float*)d_in[5];
    const float* b1    = (const float*)d_in[6];
    const float* W2    = (const float*)d_in[7];
    const float* al2   = (const float*)d_in[8];
    const float* ar2   = (const float*)d_in[9];
    const float* b2    = (const float*)d_in[10];
    const float* Wp    = (const float*)d_in[11];
    const float* bp    = (const float*)d_in[12];
    float* out = (float*)d_out;

    const int E = in_sizes[1];

    float *z, *acc1, *acc2, *el, *er;
    int *cnt, *bucket;
    cudaGetSymbolAddress((void**)&z,      g_z);
    cudaGetSymbolAddress((void**)&acc1,   g_acc1);
    cudaGetSymbolAddress((void**)&acc2,   g_acc2);
    cudaGetSymbolAddress((void**)&el,     g_el);
    cudaGetSymbolAddress((void**)&er,     g_er);
    cudaGetSymbolAddress((void**)&cnt,    g_cnt);
    cudaGetSymbolAddress((void**)&bucket, g_bucket);

    const int fill_grid = ((E + 3) / 4 + 255) / 256;
    const int gemm_grid = (N_NODES + GBLK - 1) / GBLK;
    const int agg_grid  = (N_NODES + 7) / 8;

    // ---- adjacency build: memset + ONE kernel ----
    cudaMemsetAsync(cnt, 0, N_NODES * sizeof(int));
    fill_bucket_kernel<<<fill_grid, 256>>>(src, dst, E, cnt, bucket);

    // ---- layer 1 ----
    gemm_attn_kernel<<<gemm_grid, 256>>>(feats, W1, al1, ar1, b1, z, acc1, el, er);
    gat_aggregate_kernel<0><<<agg_grid, 256>>>(cnt, bucket, el, er, z, acc1, Wp, bp, out);

    // ---- layer 2 (input acc1 already ELU'd) + fused head ----
    gemm_attn_kernel<<<gemm_grid, 256>>>(acc1, W2, al2, ar2, b2, z, acc2, el, er);
    gat_aggregate_kernel<1><<<agg_grid, 256>>>(cnt, bucket, el, er, z, acc2, Wp, bp, out);
}

// round 15
// speedup vs baseline: 2.6050x; 2.6050x over previous
#include <cuda_runtime.h>
#include <cuda_fp16.h>

#define N_NODES 50000
#define HF 128          // H*F
#define H_HEADS 4
#define DEG_CAP 128     // bucket capacity; deg ~ Poisson(16), P(>128) < 1e-60
#define GBLK 128        // nodes per GEMM block
#define KCH 32          // K chunk (2 k-steps of 16)
#define XS_STRIDE 40    // fp16 per row (80B: conflict-free ldmatrix, 16B-aligned)
#define WS_STRIDE 136   // fp16 per row (272B: conflict-free ldmatrix.trans)

// ---------------- scratch (static device globals; no allocation) ----------------
__device__ float  g_z[N_NODES * HF];
__device__ float  g_acc1[N_NODES * HF];  // layer-1 base -> elu(h1)
__device__ float  g_acc2[N_NODES * HF];  // layer-2 base (residual + bias)
__device__ float  g_el[N_NODES * H_HEADS];
__device__ float  g_er[N_NODES * H_HEADS];
__device__ __half g_xh[N_NODES * HF];    // fp16 GEMM input (x)
__device__ __half g_w1h[HF * HF];
__device__ __half g_w2h[HF * HF];
__device__ int    g_cnt[N_NODES];
__device__ int    g_bucket[N_NODES * DEG_CAP];   // 25.6 MB

__device__ __forceinline__ float leaky(float v) { return v > 0.f ? v : 0.2f * v; }
__device__ __forceinline__ float elu(float v)   { return v > 0.f ? v : (__expf(v) - 1.f); }

__device__ __forceinline__ unsigned smem_u32(const void* p) {
    unsigned a;
    asm("{ .reg .u64 t; cvta.to.shared.u64 t, %1; cvt.u32.u64 %0, t; }" : "=r"(a) : "l"(p));
    return a;
}

// ---------------- bucket fill ----------------
__global__ void fill_bucket_kernel(const int* __restrict__ src, const int* __restrict__ dst,
                                   int E, int* __restrict__ cnt, int* __restrict__ bucket) {
    int i = blockIdx.x * blockDim.x + threadIdx.x;
    int e0 = i * 4;
    if (e0 + 4 <= E) {
        int4 d4 = *reinterpret_cast<const int4*>(dst + e0);
        int4 s4 = *reinterpret_cast<const int4*>(src + e0);
        int p0 = atomicAdd(&cnt[d4.x], 1);
        int p1 = atomicAdd(&cnt[d4.y], 1);
        int p2 = atomicAdd(&cnt[d4.z], 1);
        int p3 = atomicAdd(&cnt[d4.w], 1);
        bucket[d4.x * DEG_CAP + p0] = s4.x;
        bucket[d4.y * DEG_CAP + p1] = s4.y;
        bucket[d4.z * DEG_CAP + p2] = s4.z;
        bucket[d4.w * DEG_CAP + p3] = s4.w;
    } else {
        for (int e = e0; e < E; e++) {
            int dn = dst[e];
            int pos = atomicAdd(&cnt[dn], 1);
            bucket[dn * DEG_CAP + pos] = src[e];
        }
    }
}

// ---------------- converters ----------------
// feats -> fp16 xh ; base1 = feats + b1
__global__ void conv_x_kernel(const float* __restrict__ x, const float* __restrict__ bias,
                              __half* __restrict__ xh, float* __restrict__ base) {
    int idx = blockIdx.x * blockDim.x + threadIdx.x;       // float4 index
    if (idx >= N_NODES * HF / 4) return;
    float4 v = reinterpret_cast<const float4*>(x)[idx];
    int c = (idx * 4) & (HF - 1);
    float4 b = *reinterpret_cast<const float4*>(&bias[c]);
    reinterpret_cast<float4*>(base)[idx] =
        make_float4(v.x + b.x, v.y + b.y, v.z + b.z, v.w + b.w);
    __half2 h0 = __floats2half2_rn(v.x, v.y);
    __half2 h1 = __floats2half2_rn(v.z, v.w);
    uint2 u = make_uint2(*reinterpret_cast<unsigned*>(&h0), *reinterpret_cast<unsigned*>(&h1));
    reinterpret_cast<uint2*>(xh)[idx] = u;
}

// W1, W2 -> fp16
__global__ void conv_w_kernel(const float* __restrict__ W1, const float* __restrict__ W2,
                              __half* __restrict__ W1h, __half* __restrict__ W2h) {
    int i = blockIdx.x * blockDim.x + threadIdx.x;
    if (i < HF * HF) {
        W1h[i] = __float2half_rn(W1[i]);
        W2h[i] = __float2half_rn(W2[i]);
    }
}

// ---------------- K1: tensor-core GEMM (mma.sync m16n8k16 f16->f32) --------------------
// 256 threads = 8 warps; warp w owns rows w*16..w*16+15 of a 128-node tile; all 128 cols.
__global__ __launch_bounds__(256)
void gemm_attn_kernel(const __half* __restrict__ xh,
                      const __half* __restrict__ Wh,
                      const float* __restrict__ al,
                      const float* __restrict__ ar,
                      float* __restrict__ z,
                      float* __restrict__ el,
                      float* __restrict__ er)
{
    __shared__ __half xs[GBLK][XS_STRIDE];   // 10.2 KB
    __shared__ __half ws[KCH][WS_STRIDE];    //  8.7 KB

    const int tid  = threadIdx.x;
    const int w    = tid >> 5;
    const int lane = tid & 31;
    const int n0   = blockIdx.x * GBLK;

    float acc[16][4];
    #pragma unroll
    for (int nt = 0; nt < 16; nt++)
        #pragma unroll
        for (int c = 0; c < 4; c++) acc[nt][c] = 0.f;

    // ldmatrix source addresses (fixed per thread, k-step offset added later)
    const int amat = lane >> 3;                       // 0..3
    const int arow = (w << 4) + (lane & 7) + ((amat & 1) << 3);
    const int acol = (amat >> 1) << 3;                // 0 or 8
    const unsigned a_addr0 = smem_u32(&xs[arow][acol]);

    const int bl    = lane & 15;
    const int bkrow = (bl & 7) + ((bl >> 3) << 3);    // 0..15 within k-step
    const unsigned b_addr0 = smem_u32(&ws[0][0]) + (unsigned)bkrow * (WS_STRIDE * 2);

    for (int kc = 0; kc < HF; kc += KCH) {
        // ---- stage x chunk: 128 rows x 32 fp16 (512 x 16B) ----
        #pragma unroll
        for (int it = 0; it < 2; it++) {
            int i   = tid + it * 256;                 // 0..511
            int row = i >> 2, seg = i & 3;
            int n   = n0 + row;
            uint4 v = make_uint4(0u, 0u, 0u, 0u);
            if (n < N_NODES)
                v = *reinterpret_cast<const uint4*>(&xh[n * HF + kc + seg * 8]);
            *reinterpret_cast<uint4*>(&xs[row][seg * 8]) = v;
        }
        // ---- stage W chunk: 32 rows x 128 fp16 (512 x 16B) ----
        #pragma unroll
        for (int it = 0; it < 2; it++) {
            int i  = tid + it * 256;
            int k  = i >> 4, c8 = i & 15;
            uint4 v = *reinterpret_cast<const uint4*>(&Wh[(kc + k) * HF + c8 * 8]);
            *reinterpret_cast<uint4*>(&ws[k][c8 * 8]) = v;
        }
        __syncthreads();

        #pragma unroll
        for (int s = 0; s < 2; s++) {                 // k-steps of 16
            unsigned a0, a1, a2, a3;
            asm volatile("ldmatrix.sync.aligned.m8n8.x4.shared.b16 {%0,%1,%2,%3}, [%4];"
                         : "=r"(a0), "=r"(a1), "=r"(a2), "=r"(a3)
                         : "r"(a_addr0 + (unsigned)(s * 16 * 2)));
            unsigned b_base = b_addr0 + (unsigned)(s * 16 * (WS_STRIDE * 2));
            #pragma unroll
            for (int nt = 0; nt < 16; nt++) {
                unsigned b0, b1;
                asm volatile("ldmatrix.sync.aligned.m8n8.x2.trans.shared.b16 {%0,%1}, [%2];"
                             : "=r"(b0), "=r"(b1)
                             : "r"(b_base + (unsigned)(nt * 16)));
                asm volatile("mma.sync.aligned.m16n8k16.row.col.f32.f16.f16.f32 "
                             "{%0,%1,%2,%3},{%4,%5,%6,%7},{%8,%9},{%0,%1,%2,%3};"
                             : "+f"(acc[nt][0]), "+f"(acc[nt][1]),
                               "+f"(acc[nt][2]), "+f"(acc[nt][3])
                             : "r"(a0), "r"(a1), "r"(a2), "r"(a3), "r"(b0), "r"(b1));
            }
        }
        __syncthreads();
    }

    // ---- epilogue: z store + el/er head reductions ----
    const int g = lane >> 2, t = lane & 3;
    const int nr0 = n0 + (w << 4) + g;
    const int nr1 = nr0 + 8;
    const bool v0 = (nr0 < N_NODES), v1 = (nr1 < N_NODES);

    float pl0[H_HEADS], pr0[H_HEADS], pl1[H_HEADS], pr1[H_HEADS];
    #pragma unroll
    for (int h = 0; h < H_HEADS; h++) { pl0[h] = pr0[h] = pl1[h] = pr1[h] = 0.f; }

    #pragma unroll
    for (int nt = 0; nt < 16; nt++) {
        int c = nt * 8 + t * 2;
        if (v0) *reinterpret_cast<float2*>(&z[nr0 * HF + c]) = make_float2(acc[nt][0], acc[nt][1]);
        if (v1) *reinterpret_cast<float2*>(&z[nr1 * HF + c]) = make_float2(acc[nt][2], acc[nt][3]);
        float2 alv = *reinterpret_cast<const float2*>(&al[c]);
        float2 arv = *reinterpret_cast<const float2*>(&ar[c]);
        int h = nt >> 2;
        pl0[h] += acc[nt][0] * alv.x + acc[nt][1] * alv.y;
        pr0[h] += acc[nt][0] * arv.x + acc[nt][1] * arv.y;
        pl1[h] += acc[nt][2] * alv.x + acc[nt][3] * alv.y;
        pr1[h] += acc[nt][2] * arv.x + acc[nt][3] * arv.y;
    }
    #pragma unroll
    for (int h = 0; h < H_HEADS; h++) {
        float a = pl0[h], b = pr0[h], cc = pl1[h], dd = pr1[h];
        a += __shfl_down_sync(0xffffffffu, a, 2);  a += __shfl_down_sync(0xffffffffu, a, 1);
        b += __shfl_down_sync(0xffffffffu, b, 2);  b += __shfl_down_sync(0xffffffffu, b, 1);
        cc += __shfl_down_sync(0xffffffffu, cc, 2); cc += __shfl_down_sync(0xffffffffu, cc, 1);
        dd += __shfl_down_sync(0xffffffffu, dd, 2); dd += __shfl_down_sync(0xffffffffu, dd, 1);
        if (t == 0) {
            if (v0) { el[nr0 * H_HEADS + h] = a;  er[nr0 * H_HEADS + h] = b;  }
            if (v1) { el[nr1 * H_HEADS + h] = cc; er[nr1 * H_HEADS + h] = dd; }
        }
    }
}

// ---------------- single-pass softmax-free aggregate, one warp per node -----------------
// MODE 0: elu(result) -> hio ; fp16 copy -> xh (layer-2 GEMM input) ; result+b2 -> base2
// MODE 1: head-mean + projection -> out[n]
template <int MODE>
__global__ __launch_bounds__(256)
void gat_aggregate_kernel(const int* __restrict__ cnt,
                          const int* __restrict__ bucket,
                          const float* __restrict__ el, const float* __restrict__ er,
                          const float* __restrict__ z,
                          float* __restrict__ hio,
                          __half* __restrict__ xh, float* __restrict__ base2,
                          const float* __restrict__ b2,
                          const float* __restrict__ Wp, const float* __restrict__ bp,
                          float* __restrict__ out)
{
    const int wid  = threadIdx.x >> 5;
    const int lane = threadIdx.x & 31;
    const int n    = blockIdx.x * 8 + wid;
    if (n >= N_NODES) return;

    const int beg = n * DEG_CAP;
    const int d   = cnt[n];
    const int h   = lane >> 3;

    const float erh = __ldg(&er[n * H_HEADS + h]);

    float  s   = 0.f;
    float4 acc = make_float4(0.f, 0.f, 0.f, 0.f);

    for (int i = 0; i < d; ++i) {
        int   sn = __ldg(&bucket[beg + i]);                        // warp-uniform
        float ev = __expf(leaky(__ldg(&el[sn * H_HEADS + h]) + erh));
        float4 zv = *reinterpret_cast<const float4*>(z + sn * HF + lane * 4);
        s     += ev;
        acc.x += ev * zv.x;
        acc.y += ev * zv.y;
        acc.z += ev * zv.z;
        acc.w += ev * zv.w;
    }

    const float sinv = 1.f / fmaxf(s, 1e-9f);
    float4 base = *reinterpret_cast<const float4*>(hio + n * HF + lane * 4);
    acc.x = base.x + acc.x * sinv;
    acc.y = base.y + acc.y * sinv;
    acc.z = base.z + acc.z * sinv;
    acc.w = base.w + acc.w * sinv;

    if (MODE == 0) {
        acc.x = elu(acc.x); acc.y = elu(acc.y); acc.z = elu(acc.z); acc.w = elu(acc.w);
        *reinterpret_cast<float4*>(hio + n * HF + lane * 4) = acc;
        // fp16 copy for layer-2 tensor GEMM
        __half2 h0 = __floats2half2_rn(acc.x, acc.y);
        __half2 h1 = __floats2half2_rn(acc.z, acc.w);
        uint2 u = make_uint2(*reinterpret_cast<unsigned*>(&h0),
                             *reinterpret_cast<unsigned*>(&h1));
        *reinterpret_cast<uint2*>(xh + n * HF + lane * 4) = u;
        // layer-2 base = elu(h1) + b2
        float4 b4 = *reinterpret_cast<const float4*>(&b2[lane * 4]);
        *reinterpret_cast<float4*>(base2 + n * HF + lane * 4) =
            make_float4(acc.x + b4.x, acc.y + b4.y, acc.z + b4.z, acc.w + b4.w);
    } else {
        const int f0 = (lane & 7) * 4;
        float v = acc.x * Wp[f0] + acc.y * Wp[f0 + 1] + acc.z * Wp[f0 + 2] + acc.w * Wp[f0 + 3];
        #pragma unroll
        for (int off = 16; off; off >>= 1) v += __shfl_down_sync(0xffffffffu, v, off);
        if (lane == 0) out[n] = 0.25f * v + bp[0];
    }
}

// ---------------- launch ----------------
extern "C" void kernel_launch(void* const* d_in, const int* in_sizes, int n_in,
                              void* d_out, int out_size)
{
    const float* feats = (const float*)d_in[0];
    const int*   src   = (const int*)  d_in[1];
    const int*   dst   = (const int*)  d_in[2];
    const float* W1    = (const float*)d_in[3];
    const float* al1   = (const float*)d_in[4];
    const float* ar1   = (const float*)d_in[5];
    const float* b1    = (const float*)d_in[6];
    const float* W2    = (const float*)d_in[7];
    const float* al2   = (const float*)d_in[8];
    const float* ar2   = (const float*)d_in[9];
    const float* b2    = (const float*)d_in[10];
    const float* Wp    = (const float*)d_in[11];
    const float* bp    = (const float*)d_in[12];
    float* out = (float*)d_out;

    const int E = in_sizes[1];

    float *z, *acc1, *acc2, *el, *er;
    __half *xh, *w1h, *w2h;
    int *cnt, *bucket;
    cudaGetSymbolAddress((void**)&z,      g_z);
    cudaGetSymbolAddress((void**)&acc1,   g_acc1);
    cudaGetSymbolAddress((void**)&acc2,   g_acc2);
    cudaGetSymbolAddress((void**)&el,     g_el);
    cudaGetSymbolAddress((void**)&er,     g_er);
    cudaGetSymbolAddress((void**)&xh,     g_xh);
    cudaGetSymbolAddress((void**)&w1h,    g_w1h);
    cudaGetSymbolAddress((void**)&w2h,    g_w2h);
    cudaGetSymbolAddress((void**)&cnt,    g_cnt);
    cudaGetSymbolAddress((void**)&bucket, g_bucket);

    const int fill_grid = ((E + 3) / 4 + 255) / 256;
    const int conv_grid = (N_NODES * HF / 4 + 255) / 256;
    const int gemm_grid = (N_NODES + GBLK - 1) / GBLK;
    const int agg_grid  = (N_NODES + 7) / 8;

    // ---- adjacency build + fp16 conversions ----
    cudaMemsetAsync(cnt, 0, N_NODES * sizeof(int));
    fill_bucket_kernel<<<fill_grid, 256>>>(src, dst, E, cnt, bucket);
    conv_w_kernel<<<(HF * HF + 255) / 256, 256>>>(W1, W2, w1h, w2h);
    conv_x_kernel<<<conv_grid, 256>>>(feats, b1, xh, acc1);

    // ---- layer 1 ----
    gemm_attn_kernel<<<gemm_grid, 256>>>(xh, w1h, al1, ar1, z, el, er);
    gat_aggregate_kernel<0><<<agg_grid, 256>>>(cnt, bucket, el, er, z, acc1,
                                               xh, acc2, b2, Wp, bp, out);

    // ---- layer 2 (xh/acc2 prepared by aggregate<0>) ----
    gemm_attn_kernel<<<gemm_grid, 256>>>(xh, w2h, al2, ar2, z, el, er);
    gat_aggregate_kernel<1><<<agg_grid, 256>>>(cnt, bucket, el, er, z, acc2,
                                               xh, acc2, b2, Wp, bp, out);
}